// round 7
// baseline (speedup 1.0000x reference)
#include <cuda_runtime.h>
#include <cuda_bf16.h>
#include <math.h>
#include <stdint.h>

#define Nn 32768
#define Gg 256
#define Ee 262144

typedef __nv_bfloat16 bf16;

// ---------------- scratch (device globals: no allocation) ----------------
__device__ float g_deg[Nn];
__device__ float g_dinv[Nn];
__device__ float g_ahat[Gg * 16384];
__device__ float g_acc[Gg * 2];
__device__ int   g_is64;

#define DECLBF(n, sz) __device__ __align__(16) bf16 n[sz]
DECLBF(g_XHi,  Nn * 256);  DECLBF(g_XLo,  Nn * 256);
DECLBF(g_PaHi, Nn * 256);  DECLBF(g_PaLo, Nn * 256);
DECLBF(g_PxHi, Nn * 256);  DECLBF(g_PxLo, Nn * 256);
DECLBF(g_AcaHi, Nn * 256); DECLBF(g_AcaLo, Nn * 256);
DECLBF(g_AcxHi, Nn * 256); DECLBF(g_AcxLo, Nn * 256);
DECLBF(g_AfHi, Nn * 256);  DECLBF(g_AfLo, Nn * 256);
DECLBF(g_XfHi, Nn * 256);  DECLBF(g_XfLo, Nn * 256);
DECLBF(g_AhHi, Gg * 16384); DECLBF(g_AhLo, Gg * 16384);
DECLBF(g_WtHi, 4 * 65536);  DECLBF(g_WtLo, 4 * 65536);

__device__ __forceinline__ bf16* bufH(int id) {
    switch (id) {
        case 0: return g_XHi;   case 1: return g_PaHi; case 2: return g_PxHi;
        case 3: return g_AcaHi; case 4: return g_AcxHi;
        case 5: return g_AfHi;  case 6: return g_XfHi; case 7: return g_AhHi;
    }
    return g_WtHi + (-id - 1) * 65536;
}
__device__ __forceinline__ bf16* bufL(int id) {
    switch (id) {
        case 0: return g_XLo;   case 1: return g_PaLo; case 2: return g_PxLo;
        case 3: return g_AcaLo; case 4: return g_AcxLo;
        case 5: return g_AfLo;  case 6: return g_XfLo; case 7: return g_AhLo;
    }
    return g_WtLo + (-id - 1) * 65536;
}

// ---------------- helpers ----------------
__device__ __forceinline__ void bsplit(float x, bf16& h, bf16& l) {
    h = __float2bfloat16(x);
    l = __float2bfloat16(x - __bfloat162float(h));
}
__device__ __forceinline__ void mma16816(float* c, const uint32_t* a, const uint32_t* b) {
    asm volatile(
        "mma.sync.aligned.m16n8k16.row.col.f32.bf16.bf16.f32 "
        "{%0,%1,%2,%3}, {%4,%5,%6,%7}, {%8,%9}, {%0,%1,%2,%3};"
        : "+f"(c[0]), "+f"(c[1]), "+f"(c[2]), "+f"(c[3])
        : "r"(a[0]), "r"(a[1]), "r"(a[2]), "r"(a[3]), "r"(b[0]), "r"(b[1]));
}
__device__ __forceinline__ void ldsm4(uint32_t* r, uint32_t addr) {
    asm volatile("ldmatrix.sync.aligned.m8n8.x4.shared.b16 {%0,%1,%2,%3}, [%4];"
        : "=r"(r[0]), "=r"(r[1]), "=r"(r[2]), "=r"(r[3]) : "r"(addr));
}
#define CPA16(dst, src) asm volatile("cp.async.cg.shared.global [%0], [%1], 16;" :: "r"(dst), "l"(src) : "memory")
#define CPA_COMMIT()    asm volatile("cp.async.commit_group;" ::: "memory")
#define CPA_WAIT1()     asm volatile("cp.async.wait_group 1;" ::: "memory")
#define CPA_WAIT0()     asm volatile("cp.async.wait_group 0;" ::: "memory")

// ---------------- structure kernels ----------------
__device__ __forceinline__ int edge_elem(const int* __restrict__ ei32, int i) {
    return g_is64 ? ei32[2 * i] : ei32[i];
}
__global__ void k_detect(const int* __restrict__ ei32) {
    if (threadIdx.x == 0 && blockIdx.x == 0) {
        int any = 0;
        for (int k = 0; k < 128; k++) any |= ei32[2 * k + 1];
        g_is64 = (any == 0) ? 1 : 0;
    }
}
__global__ void k_init() {
    int i = blockIdx.x * blockDim.x + threadIdx.x;
    int stride = gridDim.x * blockDim.x;
    for (int j = i; j < Gg * 16384; j += stride) g_ahat[j] = 0.f;
    if (i < Nn) g_deg[i] = 0.f;
    if (i < Gg * 2) g_acc[i] = 0.f;
}
__global__ void k_deg(const int* __restrict__ ei32) {
    int e = blockIdx.x * blockDim.x + threadIdx.x;
    if (e < Ee) {
        int d = edge_elem(ei32, Ee + e);
        if ((unsigned)d < Nn) atomicAdd(&g_deg[d], 1.f);
    }
}
__global__ void k_dinv() {
    int i = blockIdx.x * blockDim.x + threadIdx.x;
    if (i < Nn) g_dinv[i] = rsqrtf(g_deg[i] + 1.f);
}
__global__ void k_scatter(const int* __restrict__ ei32) {
    int e = blockIdx.x * blockDim.x + threadIdx.x;
    if (e < Ee) {
        int s = edge_elem(ei32, e);
        int d = edge_elem(ei32, Ee + e);
        if ((unsigned)s < Nn && (unsigned)d < Nn) {
            int g = d >> 7;
            atomicAdd(&g_ahat[(g << 14) + ((d & 127) << 7) + (s & 127)],
                      g_dinv[s] * g_dinv[d]);
        }
    }
}
__global__ void k_diag() {
    int i = blockIdx.x * blockDim.x + threadIdx.x;
    if (i < Nn) {
        int g = i >> 7, l = i & 127;
        g_ahat[(g << 14) + l * 128 + l] += g_dinv[i] * g_dinv[i];
    }
}

// ---------------- split kernels ----------------
__global__ void k_splitx(const float* __restrict__ in) {
    int i = blockIdx.x * blockDim.x + threadIdx.x;
    int stride = gridDim.x * blockDim.x;
    for (int j = i; j < Nn * 256; j += stride) {
        bf16 h, l;
        bsplit(in[j], h, l);
        g_XHi[j] = h; g_XLo[j] = l;
    }
}
__global__ void k_splita() {
    int i = blockIdx.x * blockDim.x + threadIdx.x;
    int stride = gridDim.x * blockDim.x;
    for (int j = i; j < Gg * 16384; j += stride) {
        bf16 h, l;
        bsplit(g_ahat[j], h, l);
        g_AhHi[j] = h; g_AhLo[j] = l;
    }
}
__global__ void k_wsplit(const float* __restrict__ W, int widx) {
    int n = blockIdx.x, k = threadIdx.x;   // W[k][n] -> Wt[n][k]
    bf16 h, l;
    bsplit(W[k * 256 + n], h, l);
    g_WtHi[widx * 65536 + n * 256 + k] = h;
    g_WtLo[widx * 65536 + n * 256 + k] = l;
}

// ---------------- pipelined mma split-GEMM ----------------
// C[128,128] tile = A[128,K] * B[128,K]^T, 3-pass bf16 split, cp.async 2-stage, ldmatrix.
// Inner loop is PASS-OUTER: 16 independent accumulators per sweep -> no RAW chains.
// MODE 0: featGEMM  K=256, y=mb, z=path  -> feature-major out
// MODE 1: propN     K=128, y=path, z=nb  -> node-major out +bias[col] (+relu)
// MODE 2: propT     K=128, y=mb, z=path  -> feature-major out +bias[row] (+relu)
// MODE 3: bilinear  K=128, y=mb, z=nb    -> Wl contraction into g_acc
struct GArg { int aid, bid, oid; const float* bias; int relu; };

#define ST_ROW 80          // smem row stride bytes (40 bf16)
#define ST_ARR 10240       // 128*80 per array
#define ST_STAGE 40960     // 4 arrays
#define SMEM_BYTES (2 * ST_STAGE)

template <int MODE>
__global__ void __launch_bounds__(256) k_mma(GArg pA, GArg pB,
                                             int aG, int lda, int bG, int ldb, int oG,
                                             const float* __restrict__ Wl) {
    constexpr int KK = (MODE == 0) ? 256 : 128;
    constexpr int NCH = KK / 32;
    extern __shared__ __align__(16) char dynsm[];
    const uint32_t smbase = (uint32_t)__cvta_generic_to_shared(dynsm);

    const int t = threadIdx.x, lane = t & 31, wid = t >> 5;
    const int wr = wid >> 1, wc = wid & 1;
    const int g = blockIdx.x;
    int mb, nb, path;
    if (MODE == 1)      { mb = 0; path = blockIdx.y; nb = blockIdx.z; }
    else if (MODE == 3) { mb = blockIdx.y; nb = blockIdx.z; path = 0; }
    else                { mb = blockIdx.y; path = blockIdx.z; nb = 0; }
    const GArg P = path ? pB : pA;

    const bf16* AH = bufH(P.aid) + g * aG + mb * 128 * lda;
    const bf16* AL = bufL(P.aid) + g * aG + mb * 128 * lda;
    const bf16* BH = bufH(P.bid) + g * bG + nb * 128 * ldb;
    const bf16* BL = bufL(P.bid) + g * bG + nb * 128 * ldb;

    const int ldrow = t >> 2, ldseg = t & 3;          // 256 threads -> rows 0..63, seg 0..3
    auto issue = [&](int ch) {
        uint32_t sb = smbase + (ch & 1) * ST_STAGE;
#pragma unroll
        for (int i = 0; i < 2; i++) {
            int row = ldrow + i * 64;
            uint32_t dro = row * ST_ROW + ldseg * 16;
            int go = row * lda + ch * 32 + ldseg * 8;
            int gob = row * ldb + ch * 32 + ldseg * 8;
            CPA16(sb + dro,              AH + go);
            CPA16(sb + ST_ARR + dro,     AL + go);
            CPA16(sb + 2 * ST_ARR + dro, BH + gob);
            CPA16(sb + 3 * ST_ARR + dro, BL + gob);
        }
        CPA_COMMIT();
    };

    float acc[2][8][4];
#pragma unroll
    for (int i = 0; i < 2; i++)
#pragma unroll
        for (int j = 0; j < 8; j++)
#pragma unroll
            for (int q = 0; q < 4; q++) acc[i][j][q] = 0.f;

    issue(0);
    const int atile = lane >> 3, arow = lane & 7;
    for (int ch = 0; ch < NCH; ch++) {
        if (ch + 1 < NCH) { issue(ch + 1); CPA_WAIT1(); } else { CPA_WAIT0(); }
        __syncthreads();
        uint32_t sb = smbase + (ch & 1) * ST_STAGE;
#pragma unroll
        for (int ks = 0; ks < 2; ks++) {
            const int k0b = ks * 32;
            uint32_t ah[8], al[8], bh[16], bl[16];
#pragma unroll
            for (int mt = 0; mt < 2; mt++) {
                uint32_t addr = sb + (wr * 32 + mt * 16 + ((atile & 1) << 3) + arow) * ST_ROW
                                + k0b + ((atile >> 1) << 4);
                ldsm4(ah + mt * 4, addr);
                ldsm4(al + mt * 4, addr + ST_ARR);
            }
#pragma unroll
            for (int ntp = 0; ntp < 4; ntp++) {
                uint32_t baddr = sb + 2 * ST_ARR
                                 + (wc * 64 + ntp * 16 + ((atile >> 1) << 3) + arow) * ST_ROW
                                 + k0b + ((atile & 1) << 4);
                ldsm4(bh + ntp * 4, baddr);
                ldsm4(bl + ntp * 4, baddr + ST_ARR);
            }
            // pass-outer sweeps: 16 independent accumulators per sweep
#pragma unroll
            for (int mt = 0; mt < 2; mt++)
#pragma unroll
                for (int nt = 0; nt < 8; nt++)
                    mma16816(acc[mt][nt], ah + mt * 4, bh + nt * 2);
#pragma unroll
            for (int mt = 0; mt < 2; mt++)
#pragma unroll
                for (int nt = 0; nt < 8; nt++)
                    mma16816(acc[mt][nt], ah + mt * 4, bl + nt * 2);
#pragma unroll
            for (int mt = 0; mt < 2; mt++)
#pragma unroll
                for (int nt = 0; nt < 8; nt++)
                    mma16816(acc[mt][nt], al + mt * 4, bh + nt * 2);
        }
        __syncthreads();
    }

    const int gi = lane >> 2, tg = lane & 3;
    // ---------------- epilogues ----------------
    if (MODE == 3) {
        float c0 = 0.f, c1 = 0.f;
        const float2* W2 = (const float2*)Wl;
#pragma unroll
        for (int mt = 0; mt < 2; mt++)
#pragma unroll
            for (int nt = 0; nt < 8; nt++) {
                int d0 = mb * 128 + wr * 32 + mt * 16 + gi;
                int e  = nb * 128 + wc * 64 + nt * 8 + tg * 2;
                float2 w;
                w = __ldg(&W2[d0 * 256 + e]);           c0 += acc[mt][nt][0] * w.x; c1 += acc[mt][nt][0] * w.y;
                w = __ldg(&W2[d0 * 256 + e + 1]);       c0 += acc[mt][nt][1] * w.x; c1 += acc[mt][nt][1] * w.y;
                w = __ldg(&W2[(d0 + 8) * 256 + e]);     c0 += acc[mt][nt][2] * w.x; c1 += acc[mt][nt][2] * w.y;
                w = __ldg(&W2[(d0 + 8) * 256 + e + 1]); c0 += acc[mt][nt][3] * w.x; c1 += acc[mt][nt][3] * w.y;
            }
        float* red = (float*)dynsm;
        red[t] = c0; __syncthreads();
        for (int s = 128; s > 0; s >>= 1) { if (t < s) red[t] += red[t + s]; __syncthreads(); }
        if (t == 0) atomicAdd(&g_acc[g * 2], red[0]);
        __syncthreads();
        red[t] = c1; __syncthreads();
        for (int s = 128; s > 0; s >>= 1) { if (t < s) red[t] += red[t + s]; __syncthreads(); }
        if (t == 0) atomicAdd(&g_acc[g * 2 + 1], red[0]);
        return;
    }

    bf16* Oh;
    bf16* Ol;
    int ostride, ocol0;
    if (MODE == 1) { Oh = bufH(P.oid) + g * oG; Ol = bufL(P.oid) + g * oG; ostride = 256; ocol0 = nb * 128; }
    else           { Oh = bufH(P.oid) + g * oG + mb * 16384; Ol = bufL(P.oid) + g * oG + mb * 16384; ostride = 128; ocol0 = 0; }

#pragma unroll
    for (int mt = 0; mt < 2; mt++)
#pragma unroll
        for (int nt = 0; nt < 8; nt++) {
            int row0 = wr * 32 + mt * 16 + gi;
            int col  = wc * 64 + nt * 8 + tg * 2;
#pragma unroll
            for (int half = 0; half < 2; half++) {
                int row = row0 + half * 8;
                float v0 = acc[mt][nt][half * 2];
                float v1 = acc[mt][nt][half * 2 + 1];
                if (MODE == 1) {
                    v0 += __ldg(&P.bias[ocol0 + col]);
                    v1 += __ldg(&P.bias[ocol0 + col + 1]);
                    if (P.relu) { v0 = fmaxf(v0, 0.f); v1 = fmaxf(v1, 0.f); }
                } else if (MODE == 2) {
                    float bb = __ldg(&P.bias[mb * 128 + row]);
                    v0 += bb; v1 += bb;
                    if (P.relu) { v0 = fmaxf(v0, 0.f); v1 = fmaxf(v1, 0.f); }
                }
                bf16 h0, l0, h1, l1;
                bsplit(v0, h0, l0);
                bsplit(v1, h1, l1);
                __nv_bfloat162 hp, lp;
                hp.x = h0; hp.y = h1; lp.x = l0; lp.y = l1;
                *(__nv_bfloat162*)(Oh + row * ostride + ocol0 + col) = hp;
                *(__nv_bfloat162*)(Ol + row * ostride + ocol0 + col) = lp;
            }
        }
}

// ---------------- per-row softmax on the a2 feature-major plane (in-place) ----------------
__global__ void k_segsm2() {
    int w = threadIdx.x >> 5, l = threadIdx.x & 31;
    int row = blockIdx.x * 8 + w;   // 65536 rows of 128
    bf16* ph = g_AfHi + row * 128;
    bf16* pl = g_AfLo + row * 128;
    float v[4];
#pragma unroll
    for (int i = 0; i < 4; i++)
        v[i] = __bfloat162float(ph[l * 4 + i]) + __bfloat162float(pl[l * 4 + i]);
    float m = fmaxf(fmaxf(v[0], v[1]), fmaxf(v[2], v[3]));
#pragma unroll
    for (int s = 16; s > 0; s >>= 1) m = fmaxf(m, __shfl_xor_sync(0xFFFFFFFF, m, s));
    float e[4], su = 0.f;
#pragma unroll
    for (int i = 0; i < 4; i++) { e[i] = __expf(v[i] - m); su += e[i]; }
#pragma unroll
    for (int s = 16; s > 0; s >>= 1) su += __shfl_xor_sync(0xFFFFFFFF, su, s);
    float inv = 1.f / su;
#pragma unroll
    for (int i = 0; i < 4; i++) {
        bf16 h, lo;
        bsplit(e[i] * inv, h, lo);
        ph[l * 4 + i] = h;
        pl[l * 4 + i] = lo;
    }
}

// ---------------- final bias + 2-class softmax ----------------
__global__ void k_final(const float* __restrict__ bl, float* __restrict__ out) {
    int g = blockIdx.x * blockDim.x + threadIdx.x;
    if (g < Gg) {
        float a = g_acc[2 * g] + bl[0];
        float b = g_acc[2 * g + 1] + bl[1];
        float m = fmaxf(a, b);
        float ea = __expf(a - m), eb = __expf(b - m);
        float inv = 1.f / (ea + eb);
        out[2 * g] = ea * inv;
        out[2 * g + 1] = eb * inv;
    }
}

// ---------------- launch ----------------
extern "C" void kernel_launch(void* const* d_in, const int* in_sizes, int n_in,
                              void* d_out, int out_size) {
    const float* x    = (const float*)d_in[0];
    const int*   ei32 = (const int*)d_in[1];
    const float* Wa1 = (const float*)d_in[3];
    const float* ba1 = (const float*)d_in[4];
    const float* Wa2 = (const float*)d_in[5];
    const float* ba2 = (const float*)d_in[6];
    const float* Wx1 = (const float*)d_in[7];
    const float* bx1 = (const float*)d_in[8];
    const float* Wx2 = (const float*)d_in[9];
    const float* bx2 = (const float*)d_in[10];
    const float* Wl  = (const float*)d_in[11];
    const float* bl  = (const float*)d_in[12];
    float* out = (float*)d_out;

    static int smem_set = 0;
    if (!smem_set) {
        cudaFuncSetAttribute(k_mma<0>, cudaFuncAttributeMaxDynamicSharedMemorySize, SMEM_BYTES);
        cudaFuncSetAttribute(k_mma<1>, cudaFuncAttributeMaxDynamicSharedMemorySize, SMEM_BYTES);
        cudaFuncSetAttribute(k_mma<2>, cudaFuncAttributeMaxDynamicSharedMemorySize, SMEM_BYTES);
        cudaFuncSetAttribute(k_mma<3>, cudaFuncAttributeMaxDynamicSharedMemorySize, SMEM_BYTES);
        smem_set = 1;
    }

    // structure
    k_detect<<<1, 32>>>(ei32);
    k_init<<<128, 256>>>();
    k_deg<<<Ee / 256, 256>>>(ei32);
    k_dinv<<<Nn / 256, 256>>>();
    k_scatter<<<Ee / 256, 256>>>(ei32);
    k_diag<<<Nn / 256, 256>>>();

    // splits
    k_splita<<<2048, 256>>>();
    k_splitx<<<4096, 256>>>(x);
    k_wsplit<<<256, 256>>>(Wa1, 0);
    k_wsplit<<<256, 256>>>(Wa2, 1);
    k_wsplit<<<256, 256>>>(Wx1, 2);
    k_wsplit<<<256, 256>>>(Wx2, 3);

    // ids: 0=X 1=Pa 2=Px 3=Aca 4=Acx 5=Af 6=Xf 7=Ahat; neg = Wt(-1..-4)
    dim3 gq(Gg, 2, 2);
    GArg pa, pb;

    // layer-1 feature GEMMs (both paths)
    pa = {-1, 0, 1, nullptr, 0}; pb = {-3, 0, 2, nullptr, 0};
    k_mma<0><<<gq, 256, SMEM_BYTES>>>(pa, pb, 0, 256, 32768, 256, 32768, nullptr);
    // layer-1 propagation (both paths): y=path, z=nb
    pa = {7, 1, 3, ba1, 1}; pb = {7, 2, 4, bx1, 1};
    k_mma<1><<<gq, 256, SMEM_BYTES>>>(pa, pb, 16384, 128, 32768, 128, 32768, nullptr);
    // layer-2 feature GEMMs
    pa = {-2, 3, 1, nullptr, 0}; pb = {-4, 4, 2, nullptr, 0};
    k_mma<0><<<gq, 256, SMEM_BYTES>>>(pa, pb, 0, 256, 32768, 256, 32768, nullptr);
    // layer-2 propagation, transposed (both paths): y=mb, z=path
    pa = {1, 7, 5, ba2, 0}; pb = {2, 7, 6, bx2, 1};
    k_mma<2><<<gq, 256, SMEM_BYTES>>>(pa, pb, 32768, 128, 16384, 128, 32768, nullptr);

    k_segsm2<<<8192, 256>>>();

    // bilinear + head
    pa = {5, 6, 0, nullptr, 0};
    k_mma<3><<<gq, 256, SMEM_BYTES>>>(pa, pa, 32768, 128, 32768, 128, 0, Wl);
    k_final<<<1, 256>>>(bl, out);
}

// round 9
// speedup vs baseline: 1.4000x; 1.4000x over previous
#include <cuda_runtime.h>
#include <cuda_fp16.h>
#include <math.h>
#include <stdint.h>

#define Nn 32768
#define Gg 256
#define Ee 262144

typedef __half hf;

// ---------------- scratch (device globals: no allocation) ----------------
__device__ float g_deg[Nn];
__device__ float g_dinv[Nn];
__device__ float g_ahat[Gg * 16384];
__device__ float g_acc[Gg * 2];
__device__ int   g_is64;

#define DECLHF(n, sz) __device__ __align__(16) hf n[sz]
DECLHF(g_XHi,  Nn * 256);  DECLHF(g_XLo,  Nn * 256);
DECLHF(g_PaHi, Nn * 256);  DECLHF(g_PaLo, Nn * 256);
DECLHF(g_PxHi, Nn * 256);  DECLHF(g_PxLo, Nn * 256);
DECLHF(g_AcaHi, Nn * 256); DECLHF(g_AcaLo, Nn * 256);
DECLHF(g_AcxHi, Nn * 256); DECLHF(g_AcxLo, Nn * 256);
DECLHF(g_AfHi, Nn * 256);  DECLHF(g_AfLo, Nn * 256);
DECLHF(g_XfHi, Nn * 256);  DECLHF(g_XfLo, Nn * 256);
DECLHF(g_AhHi, Gg * 16384); DECLHF(g_AhLo, Gg * 16384);
DECLHF(g_WtHi, 4 * 65536);  DECLHF(g_WtLo, 4 * 65536);

__device__ __forceinline__ hf* bufH(int id) {
    switch (id) {
        case 0: return g_XHi;   case 1: return g_PaHi; case 2: return g_PxHi;
        case 3: return g_AcaHi; case 4: return g_AcxHi;
        case 5: return g_AfHi;  case 6: return g_XfHi; case 7: return g_AhHi;
    }
    return g_WtHi + (-id - 1) * 65536;
}
__device__ __forceinline__ hf* bufL(int id) {
    switch (id) {
        case 0: return g_XLo;   case 1: return g_PaLo; case 2: return g_PxLo;
        case 3: return g_AcaLo; case 4: return g_AcxLo;
        case 5: return g_AfLo;  case 6: return g_XfLo; case 7: return g_AhLo;
    }
    return g_WtLo + (-id - 1) * 65536;
}

// ---------------- fp16 2-term split ----------------
__device__ __forceinline__ void hsplit(float x, hf& h, hf& l) {
    h = __float2half_rn(x);
    l = __float2half_rn(x - __half2float(h));
}

// ---------------- mma.sync m16n8k16 fp16 (sm_80+, valid on sm_100) ----------------
__device__ __forceinline__ void mma16816(float* c, const uint32_t* a, const uint32_t* b) {
    asm volatile(
        "mma.sync.aligned.m16n8k16.row.col.f32.f16.f16.f32 "
        "{%0,%1,%2,%3}, {%4,%5,%6,%7}, {%8,%9}, {%0,%1,%2,%3};"
        : "+f"(c[0]), "+f"(c[1]), "+f"(c[2]), "+f"(c[3])
        : "r"(a[0]), "r"(a[1]), "r"(a[2]), "r"(a[3]), "r"(b[0]), "r"(b[1]));
}
__device__ __forceinline__ void ldsm4(uint32_t* r, uint32_t addr) {
    asm volatile("ldmatrix.sync.aligned.m8n8.x4.shared.b16 {%0,%1,%2,%3}, [%4];"
        : "=r"(r[0]), "=r"(r[1]), "=r"(r[2]), "=r"(r[3]) : "r"(addr));
}
#define CPA16(dst, src) asm volatile("cp.async.cg.shared.global [%0], [%1], 16;" :: "r"(dst), "l"(src) : "memory")
#define CPA_COMMIT()    asm volatile("cp.async.commit_group;" ::: "memory")
#define CPA_WAIT1()     asm volatile("cp.async.wait_group 1;" ::: "memory")
#define CPA_WAIT0()     asm volatile("cp.async.wait_group 0;" ::: "memory")

// ---------------- structure kernels ----------------
__device__ __forceinline__ int edge_elem(const int* __restrict__ ei32, int i) {
    return g_is64 ? ei32[2 * i] : ei32[i];
}
__global__ void k_detect(const int* __restrict__ ei32) {
    if (threadIdx.x == 0 && blockIdx.x == 0) {
        int any = 0;
        for (int k = 0; k < 128; k++) any |= ei32[2 * k + 1];
        g_is64 = (any == 0) ? 1 : 0;
    }
}
__global__ void k_init() {
    int i = blockIdx.x * blockDim.x + threadIdx.x;
    int stride = gridDim.x * blockDim.x;
    for (int j = i; j < Gg * 16384; j += stride) g_ahat[j] = 0.f;
    if (i < Nn) g_deg[i] = 0.f;
    if (i < Gg * 2) g_acc[i] = 0.f;
}
__global__ void k_deg(const int* __restrict__ ei32) {
    int e = blockIdx.x * blockDim.x + threadIdx.x;
    if (e < Ee) {
        int d = edge_elem(ei32, Ee + e);
        if ((unsigned)d < Nn) atomicAdd(&g_deg[d], 1.f);
    }
}
__global__ void k_dinv() {
    int i = blockIdx.x * blockDim.x + threadIdx.x;
    if (i < Nn) g_dinv[i] = rsqrtf(g_deg[i] + 1.f);
}
__global__ void k_scatter(const int* __restrict__ ei32) {
    int e = blockIdx.x * blockDim.x + threadIdx.x;
    if (e < Ee) {
        int s = edge_elem(ei32, e);
        int d = edge_elem(ei32, Ee + e);
        if ((unsigned)s < Nn && (unsigned)d < Nn) {
            int g = d >> 7;
            atomicAdd(&g_ahat[(g << 14) + ((d & 127) << 7) + (s & 127)],
                      g_dinv[s] * g_dinv[d]);
        }
    }
}
__global__ void k_diag() {
    int i = blockIdx.x * blockDim.x + threadIdx.x;
    if (i < Nn) {
        int g = i >> 7, l = i & 127;
        g_ahat[(g << 14) + l * 128 + l] += g_dinv[i] * g_dinv[i];
    }
}

// ---------------- split kernels ----------------
__global__ void k_splitx(const float* __restrict__ in) {
    int i = blockIdx.x * blockDim.x + threadIdx.x;
    int stride = gridDim.x * blockDim.x;
    for (int j = i; j < Nn * 256; j += stride) {
        hf h, l;
        hsplit(in[j], h, l);
        g_XHi[j] = h; g_XLo[j] = l;
    }
}
__global__ void k_splita() {
    int i = blockIdx.x * blockDim.x + threadIdx.x;
    int stride = gridDim.x * blockDim.x;
    for (int j = i; j < Gg * 16384; j += stride) {
        hf h, l;
        hsplit(g_ahat[j], h, l);
        g_AhHi[j] = h; g_AhLo[j] = l;
    }
}
__global__ void k_wsplit(const float* __restrict__ W, int widx) {
    int n = blockIdx.x, k = threadIdx.x;   // W[k][n] -> Wt[n][k]
    hf h, l;
    hsplit(W[k * 256 + n], h, l);
    g_WtHi[widx * 65536 + n * 256 + k] = h;
    g_WtLo[widx * 65536 + n * 256 + k] = l;
}

// ---------------- pipelined mma split-GEMM (fp16, 2-pass: A split, B hi-only) ----------------
// C[128,128] tile = (A_hi + A_lo)[128,K] * B_hi[128,K]^T
// MODE 0: featGEMM  K=256, y=mb, z=path  -> feature-major out
// MODE 1: propN     K=128, y=path, z=nb  -> node-major out +bias[col] (+relu)
// MODE 2: propT     K=128, y=mb, z=path  -> feature-major out +bias[row] (+relu)
// MODE 3: bilinear  K=128, y=mb, z=nb    -> Wl contraction into g_acc
struct GArg { int aid, bid, oid; const float* bias; int relu; };

#define ST_ROW 80          // smem row stride bytes (40 halves): 16B-aligned, ldsm-conflict-free
#define ST_ARR 10240       // 128*80 per array
#define ST_STAGE 30720     // 3 arrays (AH, AL, BH)
#define SMEM_BYTES (2 * ST_STAGE)

template <int MODE>
__global__ void __launch_bounds__(256) k_mma(GArg pA, GArg pB,
                                             int aG, int lda, int bG, int ldb, int oG,
                                             const float* __restrict__ Wl) {
    constexpr int KK = (MODE == 0) ? 256 : 128;
    constexpr int NCH = KK / 32;
    extern __shared__ __align__(16) char dynsm[];
    const uint32_t smbase = (uint32_t)__cvta_generic_to_shared(dynsm);

    const int t = threadIdx.x, lane = t & 31, wid = t >> 5;
    const int wr = wid >> 1, wc = wid & 1;
    const int g = blockIdx.x;
    int mb, nb, path;
    if (MODE == 1)      { mb = 0; path = blockIdx.y; nb = blockIdx.z; }
    else if (MODE == 3) { mb = blockIdx.y; nb = blockIdx.z; path = 0; }
    else                { mb = blockIdx.y; path = blockIdx.z; nb = 0; }
    const GArg P = path ? pB : pA;

    const hf* AH = bufH(P.aid) + g * aG + mb * 128 * lda;
    const hf* AL = bufL(P.aid) + g * aG + mb * 128 * lda;
    const hf* BH = bufH(P.bid) + g * bG + nb * 128 * ldb;

    const int ldrow = t >> 2, ldseg = t & 3;          // 256 threads -> rows 0..63, seg 0..3
    auto issue = [&](int ch) {
        uint32_t sb = smbase + (ch & 1) * ST_STAGE;
#pragma unroll
        for (int i = 0; i < 2; i++) {
            int row = ldrow + i * 64;
            uint32_t dro = row * ST_ROW + ldseg * 16;
            int go = row * lda + ch * 32 + ldseg * 8;
            int gob = row * ldb + ch * 32 + ldseg * 8;
            CPA16(sb + dro,              AH + go);
            CPA16(sb + ST_ARR + dro,     AL + go);
            CPA16(sb + 2 * ST_ARR + dro, BH + gob);
        }
        CPA_COMMIT();
    };

    float acc[2][8][4];
#pragma unroll
    for (int i = 0; i < 2; i++)
#pragma unroll
        for (int j = 0; j < 8; j++)
#pragma unroll
            for (int q = 0; q < 4; q++) acc[i][j][q] = 0.f;

    issue(0);
    const int atile = lane >> 3, arow = lane & 7;
    for (int ch = 0; ch < NCH; ch++) {
        if (ch + 1 < NCH) { issue(ch + 1); CPA_WAIT1(); } else { CPA_WAIT0(); }
        __syncthreads();
        uint32_t sb = smbase + (ch & 1) * ST_STAGE;
#pragma unroll
        for (int ks = 0; ks < 2; ks++) {
            const int k0b = ks * 32;
            uint32_t ah[8], al[8];
#pragma unroll
            for (int mt = 0; mt < 2; mt++) {
                uint32_t addr = sb + (wr * 32 + mt * 16 + ((atile & 1) << 3) + arow) * ST_ROW
                                + k0b + ((atile >> 1) << 4);
                ldsm4(ah + mt * 4, addr);
                ldsm4(al + mt * 4, addr + ST_ARR);
            }
#pragma unroll
            for (int ntp = 0; ntp < 4; ntp++) {
                uint32_t baddr = sb + 2 * ST_ARR
                                 + (wc * 64 + ntp * 16 + ((atile >> 1) << 3) + arow) * ST_ROW
                                 + k0b + ((atile & 1) << 4);
                uint32_t bh2[4];
                ldsm4(bh2, baddr);
#pragma unroll
                for (int q2 = 0; q2 < 2; q2++) {
                    int nt = ntp * 2 + q2;
#pragma unroll
                    for (int mt = 0; mt < 2; mt++) {
                        mma16816(acc[mt][nt], ah + mt * 4, bh2 + q2 * 2);
                        mma16816(acc[mt][nt], al + mt * 4, bh2 + q2 * 2);
                    }
                }
            }
        }
        __syncthreads();
    }

    const int gi = lane >> 2, tg = lane & 3;
    // ---------------- epilogues ----------------
    if (MODE == 3) {
        float c0 = 0.f, c1 = 0.f;
        const float2* W2 = (const float2*)Wl;
#pragma unroll
        for (int mt = 0; mt < 2; mt++)
#pragma unroll
            for (int nt = 0; nt < 8; nt++) {
                int d0 = mb * 128 + wr * 32 + mt * 16 + gi;
                int e  = nb * 128 + wc * 64 + nt * 8 + tg * 2;
                float2 w;
                w = __ldg(&W2[d0 * 256 + e]);           c0 += acc[mt][nt][0] * w.x; c1 += acc[mt][nt][0] * w.y;
                w = __ldg(&W2[d0 * 256 + e + 1]);       c0 += acc[mt][nt][1] * w.x; c1 += acc[mt][nt][1] * w.y;
                w = __ldg(&W2[(d0 + 8) * 256 + e]);     c0 += acc[mt][nt][2] * w.x; c1 += acc[mt][nt][2] * w.y;
                w = __ldg(&W2[(d0 + 8) * 256 + e + 1]); c0 += acc[mt][nt][3] * w.x; c1 += acc[mt][nt][3] * w.y;
            }
        float* red = (float*)dynsm;
        red[t] = c0; __syncthreads();
        for (int s = 128; s > 0; s >>= 1) { if (t < s) red[t] += red[t + s]; __syncthreads(); }
        if (t == 0) atomicAdd(&g_acc[g * 2], red[0]);
        __syncthreads();
        red[t] = c1; __syncthreads();
        for (int s = 128; s > 0; s >>= 1) { if (t < s) red[t] += red[t + s]; __syncthreads(); }
        if (t == 0) atomicAdd(&g_acc[g * 2 + 1], red[0]);
        return;
    }

    hf* Oh;
    hf* Ol;
    int ostride, ocol0;
    if (MODE == 1) { Oh = bufH(P.oid) + g * oG; Ol = bufL(P.oid) + g * oG; ostride = 256; ocol0 = nb * 128; }
    else           { Oh = bufH(P.oid) + g * oG + mb * 16384; Ol = bufL(P.oid) + g * oG + mb * 16384; ostride = 128; ocol0 = 0; }

#pragma unroll
    for (int mt = 0; mt < 2; mt++)
#pragma unroll
        for (int nt = 0; nt < 8; nt++) {
            int row0 = wr * 32 + mt * 16 + gi;
            int col  = wc * 64 + nt * 8 + tg * 2;
#pragma unroll
            for (int half = 0; half < 2; half++) {
                int row = row0 + half * 8;
                float v0 = acc[mt][nt][half * 2];
                float v1 = acc[mt][nt][half * 2 + 1];
                if (MODE == 1) {
                    v0 += __ldg(&P.bias[ocol0 + col]);
                    v1 += __ldg(&P.bias[ocol0 + col + 1]);
                    if (P.relu) { v0 = fmaxf(v0, 0.f); v1 = fmaxf(v1, 0.f); }
                } else if (MODE == 2) {
                    float bb = __ldg(&P.bias[mb * 128 + row]);
                    v0 += bb; v1 += bb;
                    if (P.relu) { v0 = fmaxf(v0, 0.f); v1 = fmaxf(v1, 0.f); }
                }
                hf h0, l0, h1, l1;
                hsplit(v0, h0, l0);
                hsplit(v1, h1, l1);
                __half2 hp, lp;
                hp.x = h0; hp.y = h1; lp.x = l0; lp.y = l1;
                *(__half2*)(Oh + row * ostride + ocol0 + col) = hp;
                *(__half2*)(Ol + row * ostride + ocol0 + col) = lp;
            }
        }
}

// ---------------- per-row softmax on the a2 feature-major plane (in-place) ----------------
__global__ void k_segsm2() {
    int w = threadIdx.x >> 5, l = threadIdx.x & 31;
    int row = blockIdx.x * 8 + w;   // 65536 rows of 128
    hf* ph = g_AfHi + row * 128;
    hf* pl = g_AfLo + row * 128;
    float v[4];
#pragma unroll
    for (int i = 0; i < 4; i++)
        v[i] = __half2float(ph[l * 4 + i]) + __half2float(pl[l * 4 + i]);
    float m = fmaxf(fmaxf(v[0], v[1]), fmaxf(v[2], v[3]));
#pragma unroll
    for (int s = 16; s > 0; s >>= 1) m = fmaxf(m, __shfl_xor_sync(0xFFFFFFFF, m, s));
    float e[4], su = 0.f;
#pragma unroll
    for (int i = 0; i < 4; i++) { e[i] = __expf(v[i] - m); su += e[i]; }
#pragma unroll
    for (int s = 16; s > 0; s >>= 1) su += __shfl_xor_sync(0xFFFFFFFF, su, s);
    float inv = 1.f / su;
#pragma unroll
    for (int i = 0; i < 4; i++) {
        hf h, lo;
        hsplit(e[i] * inv, h, lo);
        ph[l * 4 + i] = h;
        pl[l * 4 + i] = lo;
    }
}

// ---------------- final bias + 2-class softmax ----------------
__global__ void k_final(const float* __restrict__ bl, float* __restrict__ out) {
    int g = blockIdx.x * blockDim.x + threadIdx.x;
    if (g < Gg) {
        float a = g_acc[2 * g] + bl[0];
        float b = g_acc[2 * g + 1] + bl[1];
        float m = fmaxf(a, b);
        float ea = __expf(a - m), eb = __expf(b - m);
        float inv = 1.f / (ea + eb);
        out[2 * g] = ea * inv;
        out[2 * g + 1] = eb * inv;
    }
}

// ---------------- launch ----------------
extern "C" void kernel_launch(void* const* d_in, const int* in_sizes, int n_in,
                              void* d_out, int out_size) {
    const float* x    = (const float*)d_in[0];
    const int*   ei32 = (const int*)d_in[1];
    const float* Wa1 = (const float*)d_in[3];
    const float* ba1 = (const float*)d_in[4];
    const float* Wa2 = (const float*)d_in[5];
    const float* ba2 = (const float*)d_in[6];
    const float* Wx1 = (const float*)d_in[7];
    const float* bx1 = (const float*)d_in[8];
    const float* Wx2 = (const float*)d_in[9];
    const float* bx2 = (const float*)d_in[10];
    const float* Wl  = (const float*)d_in[11];
    const float* bl  = (const float*)d_in[12];
    float* out = (float*)d_out;

    static int smem_set = 0;
    if (!smem_set) {
        cudaFuncSetAttribute(k_mma<0>, cudaFuncAttributeMaxDynamicSharedMemorySize, SMEM_BYTES);
        cudaFuncSetAttribute(k_mma<1>, cudaFuncAttributeMaxDynamicSharedMemorySize, SMEM_BYTES);
        cudaFuncSetAttribute(k_mma<2>, cudaFuncAttributeMaxDynamicSharedMemorySize, SMEM_BYTES);
        cudaFuncSetAttribute(k_mma<3>, cudaFuncAttributeMaxDynamicSharedMemorySize, SMEM_BYTES);
        smem_set = 1;
    }

    // structure
    k_detect<<<1, 32>>>(ei32);
    k_init<<<128, 256>>>();
    k_deg<<<Ee / 256, 256>>>(ei32);
    k_dinv<<<Nn / 256, 256>>>();
    k_scatter<<<Ee / 256, 256>>>(ei32);
    k_diag<<<Nn / 256, 256>>>();

    // splits
    k_splita<<<2048, 256>>>();
    k_splitx<<<4096, 256>>>(x);
    k_wsplit<<<256, 256>>>(Wa1, 0);
    k_wsplit<<<256, 256>>>(Wa2, 1);
    k_wsplit<<<256, 256>>>(Wx1, 2);
    k_wsplit<<<256, 256>>>(Wx2, 3);

    // ids: 0=X 1=Pa 2=Px 3=Aca 4=Acx 5=Af 6=Xf 7=Ahat; neg = Wt(-1..-4)
    dim3 gq(Gg, 2, 2);
    GArg pa, pb;

    // layer-1 feature GEMMs (both paths)
    pa = {-1, 0, 1, nullptr, 0}; pb = {-3, 0, 2, nullptr, 0};
    k_mma<0><<<gq, 256, SMEM_BYTES>>>(pa, pb, 0, 256, 32768, 256, 32768, nullptr);
    // layer-1 propagation (both paths): y=path, z=nb
    pa = {7, 1, 3, ba1, 1}; pb = {7, 2, 4, bx1, 1};
    k_mma<1><<<gq, 256, SMEM_BYTES>>>(pa, pb, 16384, 128, 32768, 128, 32768, nullptr);
    // layer-2 feature GEMMs
    pa = {-2, 3, 1, nullptr, 0}; pb = {-4, 4, 2, nullptr, 0};
    k_mma<0><<<gq, 256, SMEM_BYTES>>>(pa, pb, 0, 256, 32768, 256, 32768, nullptr);
    // layer-2 propagation, transposed (both paths): y=mb, z=path
    pa = {1, 7, 5, ba2, 0}; pb = {2, 7, 6, bx2, 1};
    k_mma<2><<<gq, 256, SMEM_BYTES>>>(pa, pb, 32768, 128, 16384, 128, 32768, nullptr);

    k_segsm2<<<8192, 256>>>();

    // bilinear + head
    pa = {5, 6, 0, nullptr, 0};
    k_mma<3><<<gq, 256, SMEM_BYTES>>>(pa, pa, 32768, 128, 32768, 128, 0, Wl);
    k_final<<<1, 256>>>(bl, out);
}

// round 10
// speedup vs baseline: 1.5946x; 1.1390x over previous
#include <cuda_runtime.h>
#include <cuda_fp16.h>
#include <math.h>
#include <stdint.h>

#define Nn 32768
#define Gg 256
#define Ee 262144

typedef __half hf;

// ---------------- scratch (device globals: no allocation) ----------------
__device__ float g_deg[Nn];
__device__ float g_dinv[Nn];
__device__ float g_ahat[Gg * 16384];
__device__ float g_acc[Gg * 2];
__device__ int   g_is64;

#define DECLHF(n, sz) __device__ __align__(16) hf n[sz]
DECLHF(g_XHi,  Nn * 256);                     // X: B-only -> hi plane only
DECLHF(g_PaHi, Nn * 256);  DECLHF(g_PaLo, Nn * 256);
DECLHF(g_PxHi, Nn * 256);  DECLHF(g_PxLo, Nn * 256);
DECLHF(g_AcaHi, Nn * 256);                    // Act planes: B-only -> hi only
DECLHF(g_AcxHi, Nn * 256);
DECLHF(g_AfHi, Nn * 256);  DECLHF(g_AfLo, Nn * 256);
DECLHF(g_XfHi, Nn * 256);                     // Xf: B-only -> hi only
DECLHF(g_AhHi, Gg * 16384); DECLHF(g_AhLo, Gg * 16384);
DECLHF(g_WtHi, 4 * 65536);  DECLHF(g_WtLo, 4 * 65536);

__device__ __forceinline__ hf* bufH(int id) {
    switch (id) {
        case 0: return g_XHi;   case 1: return g_PaHi; case 2: return g_PxHi;
        case 3: return g_AcaHi; case 4: return g_AcxHi;
        case 5: return g_AfHi;  case 6: return g_XfHi; case 7: return g_AhHi;
    }
    return g_WtHi + (-id - 1) * 65536;
}
// lo planes exist only for buffers consumed as the A operand
__device__ __forceinline__ hf* bufL(int id) {
    switch (id) {
        case 1: return g_PaLo; case 2: return g_PxLo;
        case 5: return g_AfLo; case 7: return g_AhLo;
    }
    return g_WtLo + (-id - 1) * 65536;
}

// ---------------- fp16 2-term split ----------------
__device__ __forceinline__ void hsplit(float x, hf& h, hf& l) {
    h = __float2half_rn(x);
    l = __float2half_rn(x - __half2float(h));
}

// ---------------- mma.sync m16n8k16 fp16 ----------------
__device__ __forceinline__ void mma16816(float* c, const uint32_t* a, const uint32_t* b) {
    asm volatile(
        "mma.sync.aligned.m16n8k16.row.col.f32.f16.f16.f32 "
        "{%0,%1,%2,%3}, {%4,%5,%6,%7}, {%8,%9}, {%0,%1,%2,%3};"
        : "+f"(c[0]), "+f"(c[1]), "+f"(c[2]), "+f"(c[3])
        : "r"(a[0]), "r"(a[1]), "r"(a[2]), "r"(a[3]), "r"(b[0]), "r"(b[1]));
}
__device__ __forceinline__ void ldsm4(uint32_t* r, uint32_t addr) {
    asm volatile("ldmatrix.sync.aligned.m8n8.x4.shared.b16 {%0,%1,%2,%3}, [%4];"
        : "=r"(r[0]), "=r"(r[1]), "=r"(r[2]), "=r"(r[3]) : "r"(addr));
}
#define CPA16(dst, src) asm volatile("cp.async.cg.shared.global [%0], [%1], 16;" :: "r"(dst), "l"(src) : "memory")
#define CPA_COMMIT()    asm volatile("cp.async.commit_group;" ::: "memory")
#define CPA_WAIT1()     asm volatile("cp.async.wait_group 1;" ::: "memory")
#define CPA_WAIT0()     asm volatile("cp.async.wait_group 0;" ::: "memory")

// ---------------- structure kernels (fused) ----------------
__device__ __forceinline__ int edge_elem(const int* __restrict__ ei32, int i) {
    return g_is64 ? ei32[2 * i] : ei32[i];
}
// init: zero ahat/deg/acc + dtype detect (thread 0 of block 0)
__global__ void k_init(const int* __restrict__ ei32) {
    int i = blockIdx.x * blockDim.x + threadIdx.x;
    if (i == 0) {
        int any = 0;
        for (int k = 0; k < 128; k++) any |= ei32[2 * k + 1];
        g_is64 = (any == 0) ? 1 : 0;
    }
    int stride = gridDim.x * blockDim.x;
    for (int j = i; j < Gg * 16384; j += stride) g_ahat[j] = 0.f;
    if (i < Nn) g_deg[i] = 0.f;
    if (i < Gg * 2) g_acc[i] = 0.f;
}
__global__ void k_deg(const int* __restrict__ ei32) {
    int e = blockIdx.x * blockDim.x + threadIdx.x;
    if (e < Ee) {
        int d = edge_elem(ei32, Ee + e);
        if ((unsigned)d < Nn) atomicAdd(&g_deg[d], 1.f);
    }
}
__global__ void k_dinv() {
    int i = blockIdx.x * blockDim.x + threadIdx.x;
    if (i < Nn) g_dinv[i] = rsqrtf(g_deg[i] + 1.f);
}
// scatter edges + diagonal self-loop term (atomicAdd throughout: race-safe)
__global__ void k_scatter(const int* __restrict__ ei32) {
    int idx = blockIdx.x * blockDim.x + threadIdx.x;
    if (idx < Ee) {
        int s = edge_elem(ei32, idx);
        int d = edge_elem(ei32, Ee + idx);
        if ((unsigned)s < Nn && (unsigned)d < Nn) {
            int g = d >> 7;
            atomicAdd(&g_ahat[(g << 14) + ((d & 127) << 7) + (s & 127)],
                      g_dinv[s] * g_dinv[d]);
        }
    } else {
        int i = idx - Ee;
        if (i < Nn) {
            int g = i >> 7, l = i & 127;
            atomicAdd(&g_ahat[(g << 14) + l * 128 + l], g_dinv[i] * g_dinv[i]);
        }
    }
}
// fused splits: ahat (hi+lo) then X (hi only)
__global__ void k_split_all(const float* __restrict__ x) {
    int i = blockIdx.x * blockDim.x + threadIdx.x;
    int stride = gridDim.x * blockDim.x;
    for (int j = i; j < Gg * 16384; j += stride) {
        hf h, l;
        hsplit(g_ahat[j], h, l);
        g_AhHi[j] = h; g_AhLo[j] = l;
    }
    for (int j = i; j < Nn * 256; j += stride)
        g_XHi[j] = __float2half_rn(x[j]);
}
// all 4 weight transpose-splits in one kernel (y = which weight)
__global__ void k_wsplit4(const float* __restrict__ W0, const float* __restrict__ W1,
                          const float* __restrict__ W2, const float* __restrict__ W3) {
    int widx = blockIdx.y;
    const float* W = widx == 0 ? W0 : (widx == 1 ? W1 : (widx == 2 ? W2 : W3));
    int n = blockIdx.x, k = threadIdx.x;   // W[k][n] -> Wt[n][k]
    hf h, l;
    hsplit(W[k * 256 + n], h, l);
    g_WtHi[widx * 65536 + n * 256 + k] = h;
    g_WtLo[widx * 65536 + n * 256 + k] = l;
}

// ---------------- pipelined mma split-GEMM (fp16, 2-pass: A split, B hi-only) ----------------
struct GArg { int aid, bid, oid; const float* bias; int relu; int storelo; };

#define ST_ROW 80
#define ST_ARR 10240
#define ST_STAGE 30720
#define SMEM_BYTES (2 * ST_STAGE)

template <int MODE>
__global__ void __launch_bounds__(256, 2) k_mma(GArg pA, GArg pB,
                                                int aG, int lda, int bG, int ldb, int oG,
                                                const float* __restrict__ Wl) {
    constexpr int KK = (MODE == 0) ? 256 : 128;
    constexpr int NCH = KK / 32;
    extern __shared__ __align__(16) char dynsm[];
    const uint32_t smbase = (uint32_t)__cvta_generic_to_shared(dynsm);

    const int t = threadIdx.x, lane = t & 31, wid = t >> 5;
    const int wr = wid >> 1, wc = wid & 1;
    const int g = blockIdx.x;
    int mb, nb, path;
    if (MODE == 1)      { mb = 0; path = blockIdx.y; nb = blockIdx.z; }
    else if (MODE == 3) { mb = blockIdx.y; nb = blockIdx.z; path = 0; }
    else                { mb = blockIdx.y; path = blockIdx.z; nb = 0; }
    const GArg P = path ? pB : pA;

    const hf* AH = bufH(P.aid) + g * aG + mb * 128 * lda;
    const hf* AL = bufL(P.aid) + g * aG + mb * 128 * lda;
    const hf* BH = bufH(P.bid) + g * bG + nb * 128 * ldb;

    const int ldrow = t >> 2, ldseg = t & 3;
    auto issue = [&](int ch) {
        uint32_t sb = smbase + (ch & 1) * ST_STAGE;
#pragma unroll
        for (int i = 0; i < 2; i++) {
            int row = ldrow + i * 64;
            uint32_t dro = row * ST_ROW + ldseg * 16;
            int go = row * lda + ch * 32 + ldseg * 8;
            int gob = row * ldb + ch * 32 + ldseg * 8;
            CPA16(sb + dro,              AH + go);
            CPA16(sb + ST_ARR + dro,     AL + go);
            CPA16(sb + 2 * ST_ARR + dro, BH + gob);
        }
        CPA_COMMIT();
    };

    float acc[2][8][4];
#pragma unroll
    for (int i = 0; i < 2; i++)
#pragma unroll
        for (int j = 0; j < 8; j++)
#pragma unroll
            for (int q = 0; q < 4; q++) acc[i][j][q] = 0.f;

    issue(0);
    const int atile = lane >> 3, arow = lane & 7;
    for (int ch = 0; ch < NCH; ch++) {
        if (ch + 1 < NCH) { issue(ch + 1); CPA_WAIT1(); } else { CPA_WAIT0(); }
        __syncthreads();
        uint32_t sb = smbase + (ch & 1) * ST_STAGE;
#pragma unroll
        for (int ks = 0; ks < 2; ks++) {
            const int k0b = ks * 32;
            uint32_t ah[8], al[8];
#pragma unroll
            for (int mt = 0; mt < 2; mt++) {
                uint32_t addr = sb + (wr * 32 + mt * 16 + ((atile & 1) << 3) + arow) * ST_ROW
                                + k0b + ((atile >> 1) << 4);
                ldsm4(ah + mt * 4, addr);
                ldsm4(al + mt * 4, addr + ST_ARR);
            }
#pragma unroll
            for (int ntp = 0; ntp < 4; ntp++) {
                uint32_t baddr = sb + 2 * ST_ARR
                                 + (wc * 64 + ntp * 16 + ((atile >> 1) << 3) + arow) * ST_ROW
                                 + k0b + ((atile & 1) << 4);
                uint32_t bh2[4];
                ldsm4(bh2, baddr);
#pragma unroll
                for (int q2 = 0; q2 < 2; q2++) {
                    int nt = ntp * 2 + q2;
#pragma unroll
                    for (int mt = 0; mt < 2; mt++) {
                        mma16816(acc[mt][nt], ah + mt * 4, bh2 + q2 * 2);
                        mma16816(acc[mt][nt], al + mt * 4, bh2 + q2 * 2);
                    }
                }
            }
        }
        __syncthreads();
    }

    const int gi = lane >> 2, tg = lane & 3;
    // ---------------- epilogues ----------------
    if (MODE == 3) {
        float c0 = 0.f, c1 = 0.f;
        const float2* W2 = (const float2*)Wl;
#pragma unroll
        for (int mt = 0; mt < 2; mt++)
#pragma unroll
            for (int nt = 0; nt < 8; nt++) {
                int d0 = mb * 128 + wr * 32 + mt * 16 + gi;
                int e  = nb * 128 + wc * 64 + nt * 8 + tg * 2;
                float2 w;
                w = __ldg(&W2[d0 * 256 + e]);           c0 += acc[mt][nt][0] * w.x; c1 += acc[mt][nt][0] * w.y;
                w = __ldg(&W2[d0 * 256 + e + 1]);       c0 += acc[mt][nt][1] * w.x; c1 += acc[mt][nt][1] * w.y;
                w = __ldg(&W2[(d0 + 8) * 256 + e]);     c0 += acc[mt][nt][2] * w.x; c1 += acc[mt][nt][2] * w.y;
                w = __ldg(&W2[(d0 + 8) * 256 + e + 1]); c0 += acc[mt][nt][3] * w.x; c1 += acc[mt][nt][3] * w.y;
            }
        float* red = (float*)dynsm;
        red[t] = c0; __syncthreads();
        for (int s = 128; s > 0; s >>= 1) { if (t < s) red[t] += red[t + s]; __syncthreads(); }
        if (t == 0) atomicAdd(&g_acc[g * 2], red[0]);
        __syncthreads();
        red[t] = c1; __syncthreads();
        for (int s = 128; s > 0; s >>= 1) { if (t < s) red[t] += red[t + s]; __syncthreads(); }
        if (t == 0) atomicAdd(&g_acc[g * 2 + 1], red[0]);
        return;
    }

    hf* Oh;
    hf* Ol;
    int ostride, ocol0;
    if (MODE == 1) { Oh = bufH(P.oid) + g * oG; Ol = bufL(P.oid) + g * oG; ostride = 256; ocol0 = nb * 128; }
    else           { Oh = bufH(P.oid) + g * oG + mb * 16384; Ol = bufL(P.oid) + g * oG + mb * 16384; ostride = 128; ocol0 = 0; }
    const bool slo = P.storelo != 0;

#pragma unroll
    for (int mt = 0; mt < 2; mt++)
#pragma unroll
        for (int nt = 0; nt < 8; nt++) {
            int row0 = wr * 32 + mt * 16 + gi;
            int col  = wc * 64 + nt * 8 + tg * 2;
#pragma unroll
            for (int half = 0; half < 2; half++) {
                int row = row0 + half * 8;
                float v0 = acc[mt][nt][half * 2];
                float v1 = acc[mt][nt][half * 2 + 1];
                if (MODE == 1) {
                    v0 += __ldg(&P.bias[ocol0 + col]);
                    v1 += __ldg(&P.bias[ocol0 + col + 1]);
                    if (P.relu) { v0 = fmaxf(v0, 0.f); v1 = fmaxf(v1, 0.f); }
                } else if (MODE == 2) {
                    float bb = __ldg(&P.bias[mb * 128 + row]);
                    v0 += bb; v1 += bb;
                    if (P.relu) { v0 = fmaxf(v0, 0.f); v1 = fmaxf(v1, 0.f); }
                }
                hf h0, l0, h1, l1;
                hsplit(v0, h0, l0);
                hsplit(v1, h1, l1);
                __half2 hp, lp;
                hp.x = h0; hp.y = h1; lp.x = l0; lp.y = l1;
                *(__half2*)(Oh + row * ostride + ocol0 + col) = hp;
                if (slo) *(__half2*)(Ol + row * ostride + ocol0 + col) = lp;
            }
        }
}

// ---------------- per-row softmax on the a2 feature-major plane (in-place) ----------------
__global__ void k_segsm2() {
    int w = threadIdx.x >> 5, l = threadIdx.x & 31;
    int row = blockIdx.x * 8 + w;
    hf* ph = g_AfHi + row * 128;
    hf* pl = g_AfLo + row * 128;
    float v[4];
#pragma unroll
    for (int i = 0; i < 4; i++)
        v[i] = __half2float(ph[l * 4 + i]) + __half2float(pl[l * 4 + i]);
    float m = fmaxf(fmaxf(v[0], v[1]), fmaxf(v[2], v[3]));
#pragma unroll
    for (int s = 16; s > 0; s >>= 1) m = fmaxf(m, __shfl_xor_sync(0xFFFFFFFF, m, s));
    float e[4], su = 0.f;
#pragma unroll
    for (int i = 0; i < 4; i++) { e[i] = __expf(v[i] - m); su += e[i]; }
#pragma unroll
    for (int s = 16; s > 0; s >>= 1) su += __shfl_xor_sync(0xFFFFFFFF, su, s);
    float inv = 1.f / su;
#pragma unroll
    for (int i = 0; i < 4; i++) {
        hf h, lo;
        hsplit(e[i] * inv, h, lo);
        ph[l * 4 + i] = h;
        pl[l * 4 + i] = lo;
    }
}

// ---------------- final bias + 2-class softmax ----------------
__global__ void k_final(const float* __restrict__ bl, float* __restrict__ out) {
    int g = blockIdx.x * blockDim.x + threadIdx.x;
    if (g < Gg) {
        float a = g_acc[2 * g] + bl[0];
        float b = g_acc[2 * g + 1] + bl[1];
        float m = fmaxf(a, b);
        float ea = __expf(a - m), eb = __expf(b - m);
        float inv = 1.f / (ea + eb);
        out[2 * g] = ea * inv;
        out[2 * g + 1] = eb * inv;
    }
}

// ---------------- launch ----------------
extern "C" void kernel_launch(void* const* d_in, const int* in_sizes, int n_in,
                              void* d_out, int out_size) {
    const float* x    = (const float*)d_in[0];
    const int*   ei32 = (const int*)d_in[1];
    const float* Wa1 = (const float*)d_in[3];
    const float* ba1 = (const float*)d_in[4];
    const float* Wa2 = (const float*)d_in[5];
    const float* ba2 = (const float*)d_in[6];
    const float* Wx1 = (const float*)d_in[7];
    const float* bx1 = (const float*)d_in[8];
    const float* Wx2 = (const float*)d_in[9];
    const float* bx2 = (const float*)d_in[10];
    const float* Wl  = (const float*)d_in[11];
    const float* bl  = (const float*)d_in[12];
    float* out = (float*)d_out;

    static int smem_set = 0;
    if (!smem_set) {
        cudaFuncSetAttribute(k_mma<0>, cudaFuncAttributeMaxDynamicSharedMemorySize, SMEM_BYTES);
        cudaFuncSetAttribute(k_mma<1>, cudaFuncAttributeMaxDynamicSharedMemorySize, SMEM_BYTES);
        cudaFuncSetAttribute(k_mma<2>, cudaFuncAttributeMaxDynamicSharedMemorySize, SMEM_BYTES);
        cudaFuncSetAttribute(k_mma<3>, cudaFuncAttributeMaxDynamicSharedMemorySize, SMEM_BYTES);
        smem_set = 1;
    }

    // structure (fused)
    k_init<<<128, 256>>>(ei32);
    k_deg<<<Ee / 256, 256>>>(ei32);
    k_dinv<<<Nn / 256, 256>>>();
    k_scatter<<<(Ee + Nn) / 256, 256>>>(ei32);

    // splits (fused)
    k_split_all<<<4096, 256>>>(x);
    k_wsplit4<<<dim3(256, 4), 256>>>(Wa1, Wa2, Wx1, Wx2);

    // ids: 0=X 1=Pa 2=Px 3=Aca 4=Acx 5=Af 6=Xf 7=Ahat; neg = Wt(-1..-4)
    dim3 gq(Gg, 2, 2);
    GArg pa, pb;

    // layer-1 feature GEMMs (both paths) -> P planes (A-consumed: store lo)
    pa = {-1, 0, 1, nullptr, 0, 1}; pb = {-3, 0, 2, nullptr, 0, 1};
    k_mma<0><<<gq, 256, SMEM_BYTES>>>(pa, pb, 0, 256, 32768, 256, 32768, nullptr);
    // layer-1 propagation -> Act planes (B-only: hi only)
    pa = {7, 1, 3, ba1, 1, 0}; pb = {7, 2, 4, bx1, 1, 0};
    k_mma<1><<<gq, 256, SMEM_BYTES>>>(pa, pb, 16384, 128, 32768, 128, 32768, nullptr);
    // layer-2 feature GEMMs -> P planes (store lo)
    pa = {-2, 3, 1, nullptr, 0, 1}; pb = {-4, 4, 2, nullptr, 0, 1};
    k_mma<0><<<gq, 256, SMEM_BYTES>>>(pa, pb, 0, 256, 32768, 256, 32768, nullptr);
    // layer-2 propagation (transposed): Af needs lo (A in bilinear), Xf hi-only
    pa = {1, 7, 5, ba2, 0, 1}; pb = {2, 7, 6, bx2, 1, 0};
    k_mma<2><<<gq, 256, SMEM_BYTES>>>(pa, pb, 32768, 128, 16384, 128, 32768, nullptr);

    k_segsm2<<<8192, 256>>>();

    // bilinear + head
    pa = {5, 6, 0, nullptr, 0, 0};
    k_mma<3><<<gq, 256, SMEM_BYTES>>>(pa, pa, 32768, 128, 32768, 128, 0, Wl);
    k_final<<<1, 256>>>(bl, out);
}

// round 11
// speedup vs baseline: 2.2703x; 1.4237x over previous
#include <cuda_runtime.h>
#include <cuda_fp16.h>
#include <math.h>
#include <stdint.h>

#define Nn 32768
#define Gg 256
#define Ee 262144

typedef __half hf;

// ---------------- scratch (device globals: no allocation) ----------------
__device__ float g_deg[Nn];
__device__ float g_dinv[Nn];
__device__ float g_ahat[Gg * 16384];
__device__ float g_acc[Gg * 2];
__device__ int   g_is64;

#define DECLHF(n, sz) __device__ __align__(16) hf n[sz]
DECLHF(g_X,  Nn * 256);
DECLHF(g_Pa, Nn * 256);
DECLHF(g_Px, Nn * 256);
DECLHF(g_Aca, Nn * 256);
DECLHF(g_Acx, Nn * 256);
DECLHF(g_Af, Nn * 256);
DECLHF(g_Xf, Nn * 256);
DECLHF(g_Ah, Gg * 16384);
DECLHF(g_Wt, 4 * 65536);

__device__ __forceinline__ hf* bufsel(int id) {
    switch (id) {
        case 0: return g_X;   case 1: return g_Pa; case 2: return g_Px;
        case 3: return g_Aca; case 4: return g_Acx;
        case 5: return g_Af;  case 6: return g_Xf; case 7: return g_Ah;
    }
    return g_Wt + (-id - 1) * 65536;
}

// ---------------- mma.sync m16n8k16 fp16 ----------------
__device__ __forceinline__ void mma16816(float* c, const uint32_t* a, const uint32_t* b) {
    asm volatile(
        "mma.sync.aligned.m16n8k16.row.col.f32.f16.f16.f32 "
        "{%0,%1,%2,%3}, {%4,%5,%6,%7}, {%8,%9}, {%0,%1,%2,%3};"
        : "+f"(c[0]), "+f"(c[1]), "+f"(c[2]), "+f"(c[3])
        : "r"(a[0]), "r"(a[1]), "r"(a[2]), "r"(a[3]), "r"(b[0]), "r"(b[1]));
}
__device__ __forceinline__ void ldsm4(uint32_t* r, uint32_t addr) {
    asm volatile("ldmatrix.sync.aligned.m8n8.x4.shared.b16 {%0,%1,%2,%3}, [%4];"
        : "=r"(r[0]), "=r"(r[1]), "=r"(r[2]), "=r"(r[3]) : "r"(addr));
}
#define CPA16(dst, src) asm volatile("cp.async.cg.shared.global [%0], [%1], 16;" :: "r"(dst), "l"(src) : "memory")
#define CPA_COMMIT()    asm volatile("cp.async.commit_group;" ::: "memory")
#define CPA_WAIT1()     asm volatile("cp.async.wait_group 1;" ::: "memory")
#define CPA_WAIT0()     asm volatile("cp.async.wait_group 0;" ::: "memory")

// ---------------- structure kernels (fused) ----------------
__device__ __forceinline__ int edge_elem(const int* __restrict__ ei32, int i) {
    return g_is64 ? ei32[2 * i] : ei32[i];
}
__global__ void k_init(const int* __restrict__ ei32) {
    int i = blockIdx.x * blockDim.x + threadIdx.x;
    if (i == 0) {
        int any = 0;
        for (int k = 0; k < 128; k++) any |= ei32[2 * k + 1];
        g_is64 = (any == 0) ? 1 : 0;
    }
    int stride = gridDim.x * blockDim.x;
    for (int j = i; j < Gg * 16384; j += stride) g_ahat[j] = 0.f;
    if (i < Nn) g_deg[i] = 0.f;
    if (i < Gg * 2) g_acc[i] = 0.f;
}
__global__ void k_deg(const int* __restrict__ ei32) {
    int e = blockIdx.x * blockDim.x + threadIdx.x;
    if (e < Ee) {
        int d = edge_elem(ei32, Ee + e);
        if ((unsigned)d < Nn) atomicAdd(&g_deg[d], 1.f);
    }
}
__global__ void k_dinv() {
    int i = blockIdx.x * blockDim.x + threadIdx.x;
    if (i < Nn) g_dinv[i] = rsqrtf(g_deg[i] + 1.f);
}
__global__ void k_scatter(const int* __restrict__ ei32) {
    int idx = blockIdx.x * blockDim.x + threadIdx.x;
    if (idx < Ee) {
        int s = edge_elem(ei32, idx);
        int d = edge_elem(ei32, Ee + idx);
        if ((unsigned)s < Nn && (unsigned)d < Nn) {
            int g = d >> 7;
            atomicAdd(&g_ahat[(g << 14) + ((d & 127) << 7) + (s & 127)],
                      g_dinv[s] * g_dinv[d]);
        }
    } else {
        int i = idx - Ee;
        if (i < Nn) {
            int g = i >> 7, l = i & 127;
            atomicAdd(&g_ahat[(g << 14) + l * 128 + l], g_dinv[i] * g_dinv[i]);
        }
    }
}
// fused converts: ahat -> fp16, X -> fp16
__global__ void k_split_all(const float* __restrict__ x) {
    int i = blockIdx.x * blockDim.x + threadIdx.x;
    int stride = gridDim.x * blockDim.x;
    for (int j = i; j < Gg * 16384; j += stride)
        g_Ah[j] = __float2half_rn(g_ahat[j]);
    for (int j = i; j < Nn * 256; j += stride)
        g_X[j] = __float2half_rn(x[j]);
}
// all 4 weight transposes in one kernel
__global__ void k_wsplit4(const float* __restrict__ W0, const float* __restrict__ W1,
                          const float* __restrict__ W2, const float* __restrict__ W3) {
    int widx = blockIdx.y;
    const float* W = widx == 0 ? W0 : (widx == 1 ? W1 : (widx == 2 ? W2 : W3));
    int n = blockIdx.x, k = threadIdx.x;   // W[k][n] -> Wt[n][k]
    g_Wt[widx * 65536 + n * 256 + k] = __float2half_rn(W[k * 256 + n]);
}

// ---------------- pipelined mma GEMM (single-pass fp16) ----------------
struct GArg { int aid, bid, oid; const float* bias; int relu; };

#define ST_ROW 80
#define ST_ARR 10240
#define ST_STAGE 20480
#define SMEM_BYTES (2 * ST_STAGE)

template <int MODE>
__global__ void __launch_bounds__(256, 2) k_mma(GArg pA, GArg pB,
                                                int aG, int lda, int bG, int ldb, int oG,
                                                const float* __restrict__ Wl) {
    constexpr int KK = (MODE == 0) ? 256 : 128;
    constexpr int NCH = KK / 32;
    extern __shared__ __align__(16) char dynsm[];
    const uint32_t smbase = (uint32_t)__cvta_generic_to_shared(dynsm);

    const int t = threadIdx.x, lane = t & 31, wid = t >> 5;
    const int wr = wid >> 1, wc = wid & 1;
    const int g = blockIdx.x;
    int mb, nb, path;
    if (MODE == 1)      { mb = 0; path = blockIdx.y; nb = blockIdx.z; }
    else if (MODE == 3) { mb = blockIdx.y; nb = blockIdx.z; path = 0; }
    else                { mb = blockIdx.y; path = blockIdx.z; nb = 0; }
    const GArg P = path ? pB : pA;

    const hf* A = bufsel(P.aid) + g * aG + mb * 128 * lda;
    const hf* B = bufsel(P.bid) + g * bG + nb * 128 * ldb;

    const int ldrow = t >> 2, ldseg = t & 3;
    auto issue = [&](int ch) {
        uint32_t sb = smbase + (ch & 1) * ST_STAGE;
#pragma unroll
        for (int i = 0; i < 2; i++) {
            int row = ldrow + i * 64;
            uint32_t dro = row * ST_ROW + ldseg * 16;
            CPA16(sb + dro,          A + row * lda + ch * 32 + ldseg * 8);
            CPA16(sb + ST_ARR + dro, B + row * ldb + ch * 32 + ldseg * 8);
        }
        CPA_COMMIT();
    };

    float acc[2][8][4];
#pragma unroll
    for (int i = 0; i < 2; i++)
#pragma unroll
        for (int j = 0; j < 8; j++)
#pragma unroll
            for (int q = 0; q < 4; q++) acc[i][j][q] = 0.f;

    issue(0);
    const int atile = lane >> 3, arow = lane & 7;
    for (int ch = 0; ch < NCH; ch++) {
        if (ch + 1 < NCH) { issue(ch + 1); CPA_WAIT1(); } else { CPA_WAIT0(); }
        __syncthreads();
        uint32_t sb = smbase + (ch & 1) * ST_STAGE;
#pragma unroll
        for (int ks = 0; ks < 2; ks++) {
            const int k0b = ks * 32;
            uint32_t ah[8];
#pragma unroll
            for (int mt = 0; mt < 2; mt++) {
                uint32_t addr = sb + (wr * 32 + mt * 16 + ((atile & 1) << 3) + arow) * ST_ROW
                                + k0b + ((atile >> 1) << 4);
                ldsm4(ah + mt * 4, addr);
            }
#pragma unroll
            for (int ntp = 0; ntp < 4; ntp++) {
                uint32_t baddr = sb + ST_ARR
                                 + (wc * 64 + ntp * 16 + ((atile >> 1) << 3) + arow) * ST_ROW
                                 + k0b + ((atile & 1) << 4);
                uint32_t bh2[4];
                ldsm4(bh2, baddr);
#pragma unroll
                for (int q2 = 0; q2 < 2; q2++) {
                    int nt = ntp * 2 + q2;
#pragma unroll
                    for (int mt = 0; mt < 2; mt++)
                        mma16816(acc[mt][nt], ah + mt * 4, bh2 + q2 * 2);
                }
            }
        }
        __syncthreads();
    }

    const int gi = lane >> 2, tg = lane & 3;
    // ---------------- epilogues ----------------
    if (MODE == 3) {
        float c0 = 0.f, c1 = 0.f;
        const float2* W2 = (const float2*)Wl;
#pragma unroll
        for (int mt = 0; mt < 2; mt++)
#pragma unroll
            for (int nt = 0; nt < 8; nt++) {
                int d0 = mb * 128 + wr * 32 + mt * 16 + gi;
                int e  = nb * 128 + wc * 64 + nt * 8 + tg * 2;
                float2 w;
                w = __ldg(&W2[d0 * 256 + e]);           c0 += acc[mt][nt][0] * w.x; c1 += acc[mt][nt][0] * w.y;
                w = __ldg(&W2[d0 * 256 + e + 1]);       c0 += acc[mt][nt][1] * w.x; c1 += acc[mt][nt][1] * w.y;
                w = __ldg(&W2[(d0 + 8) * 256 + e]);     c0 += acc[mt][nt][2] * w.x; c1 += acc[mt][nt][2] * w.y;
                w = __ldg(&W2[(d0 + 8) * 256 + e + 1]); c0 += acc[mt][nt][3] * w.x; c1 += acc[mt][nt][3] * w.y;
            }
        float* red = (float*)dynsm;
        red[t] = c0; __syncthreads();
        for (int s = 128; s > 0; s >>= 1) { if (t < s) red[t] += red[t + s]; __syncthreads(); }
        if (t == 0) atomicAdd(&g_acc[g * 2], red[0]);
        __syncthreads();
        red[t] = c1; __syncthreads();
        for (int s = 128; s > 0; s >>= 1) { if (t < s) red[t] += red[t + s]; __syncthreads(); }
        if (t == 0) atomicAdd(&g_acc[g * 2 + 1], red[0]);
        return;
    }

    hf* O;
    int ostride, ocol0;
    if (MODE == 1) { O = bufsel(P.oid) + g * oG; ostride = 256; ocol0 = nb * 128; }
    else           { O = bufsel(P.oid) + g * oG + mb * 16384; ostride = 128; ocol0 = 0; }

#pragma unroll
    for (int mt = 0; mt < 2; mt++)
#pragma unroll
        for (int nt = 0; nt < 8; nt++) {
            int row0 = wr * 32 + mt * 16 + gi;
            int col  = wc * 64 + nt * 8 + tg * 2;
#pragma unroll
            for (int half = 0; half < 2; half++) {
                int row = row0 + half * 8;
                float v0 = acc[mt][nt][half * 2];
                float v1 = acc[mt][nt][half * 2 + 1];
                if (MODE == 1) {
                    v0 += __ldg(&P.bias[ocol0 + col]);
                    v1 += __ldg(&P.bias[ocol0 + col + 1]);
                    if (P.relu) { v0 = fmaxf(v0, 0.f); v1 = fmaxf(v1, 0.f); }
                } else if (MODE == 2) {
                    float bb = __ldg(&P.bias[mb * 128 + row]);
                    v0 += bb; v1 += bb;
                    if (P.relu) { v0 = fmaxf(v0, 0.f); v1 = fmaxf(v1, 0.f); }
                }
                __half2 hp;
                hp.x = __float2half_rn(v0); hp.y = __float2half_rn(v1);
                *(__half2*)(O + row * ostride + ocol0 + col) = hp;
            }
        }
}

// ---------------- per-row softmax on the a2 feature-major plane (in-place) ----------------
__global__ void k_segsm2() {
    int w = threadIdx.x >> 5, l = threadIdx.x & 31;
    int row = blockIdx.x * 8 + w;
    hf* ph = g_Af + row * 128;
    float v[4];
#pragma unroll
    for (int i = 0; i < 4; i++) v[i] = __half2float(ph[l * 4 + i]);
    float m = fmaxf(fmaxf(v[0], v[1]), fmaxf(v[2], v[3]));
#pragma unroll
    for (int s = 16; s > 0; s >>= 1) m = fmaxf(m, __shfl_xor_sync(0xFFFFFFFF, m, s));
    float e[4], su = 0.f;
#pragma unroll
    for (int i = 0; i < 4; i++) { e[i] = __expf(v[i] - m); su += e[i]; }
#pragma unroll
    for (int s = 16; s > 0; s >>= 1) su += __shfl_xor_sync(0xFFFFFFFF, su, s);
    float inv = 1.f / su;
#pragma unroll
    for (int i = 0; i < 4; i++) ph[l * 4 + i] = __float2half_rn(e[i] * inv);
}

// ---------------- final bias + 2-class softmax ----------------
__global__ void k_final(const float* __restrict__ bl, float* __restrict__ out) {
    int g = blockIdx.x * blockDim.x + threadIdx.x;
    if (g < Gg) {
        float a = g_acc[2 * g] + bl[0];
        float b = g_acc[2 * g + 1] + bl[1];
        float m = fmaxf(a, b);
        float ea = __expf(a - m), eb = __expf(b - m);
        float inv = 1.f / (ea + eb);
        out[2 * g] = ea * inv;
        out[2 * g + 1] = eb * inv;
    }
}

// ---------------- launch ----------------
extern "C" void kernel_launch(void* const* d_in, const int* in_sizes, int n_in,
                              void* d_out, int out_size) {
    const float* x    = (const float*)d_in[0];
    const int*   ei32 = (const int*)d_in[1];
    const float* Wa1 = (const float*)d_in[3];
    const float* ba1 = (const float*)d_in[4];
    const float* Wa2 = (const float*)d_in[5];
    const float* ba2 = (const float*)d_in[6];
    const float* Wx1 = (const float*)d_in[7];
    const float* bx1 = (const float*)d_in[8];
    const float* Wx2 = (const float*)d_in[9];
    const float* bx2 = (const float*)d_in[10];
    const float* Wl  = (const float*)d_in[11];
    const float* bl  = (const float*)d_in[12];
    float* out = (float*)d_out;

    static int smem_set = 0;
    if (!smem_set) {
        cudaFuncSetAttribute(k_mma<0>, cudaFuncAttributeMaxDynamicSharedMemorySize, SMEM_BYTES);
        cudaFuncSetAttribute(k_mma<1>, cudaFuncAttributeMaxDynamicSharedMemorySize, SMEM_BYTES);
        cudaFuncSetAttribute(k_mma<2>, cudaFuncAttributeMaxDynamicSharedMemorySize, SMEM_BYTES);
        cudaFuncSetAttribute(k_mma<3>, cudaFuncAttributeMaxDynamicSharedMemorySize, SMEM_BYTES);
        smem_set = 1;
    }

    // structure (fused)
    k_init<<<128, 256>>>(ei32);
    k_deg<<<Ee / 256, 256>>>(ei32);
    k_dinv<<<Nn / 256, 256>>>();
    k_scatter<<<(Ee + Nn) / 256, 256>>>(ei32);

    // converts (fused)
    k_split_all<<<4096, 256>>>(x);
    k_wsplit4<<<dim3(256, 4), 256>>>(Wa1, Wa2, Wx1, Wx2);

    // ids: 0=X 1=Pa 2=Px 3=Aca 4=Acx 5=Af 6=Xf 7=Ahat; neg = Wt(-1..-4)
    dim3 gq(Gg, 2, 2);
    GArg pa, pb;

    // layer-1 feature GEMMs (both paths)
    pa = {-1, 0, 1, nullptr, 0}; pb = {-3, 0, 2, nullptr, 0};
    k_mma<0><<<gq, 256, SMEM_BYTES>>>(pa, pb, 0, 256, 32768, 256, 32768, nullptr);
    // layer-1 propagation (both paths)
    pa = {7, 1, 3, ba1, 1}; pb = {7, 2, 4, bx1, 1};
    k_mma<1><<<gq, 256, SMEM_BYTES>>>(pa, pb, 16384, 128, 32768, 128, 32768, nullptr);
    // layer-2 feature GEMMs
    pa = {-2, 3, 1, nullptr, 0}; pb = {-4, 4, 2, nullptr, 0};
    k_mma<0><<<gq, 256, SMEM_BYTES>>>(pa, pb, 0, 256, 32768, 256, 32768, nullptr);
    // layer-2 propagation (transposed)
    pa = {1, 7, 5, ba2, 0}; pb = {2, 7, 6, bx2, 1};
    k_mma<2><<<gq, 256, SMEM_BYTES>>>(pa, pb, 32768, 128, 16384, 128, 32768, nullptr);

    k_segsm2<<<8192, 256>>>();

    // bilinear + head
    pa = {5, 6, 0, nullptr, 0};
    k_mma<3><<<gq, 256, SMEM_BYTES>>>(pa, pa, 32768, 128, 32768, 128, 0, Wl);
    k_final<<<1, 256>>>(bl, out);
}